// round 7
// baseline (speedup 1.0000x reference)
#include <cuda_runtime.h>
#include <cuda_fp16.h>
#include <cstdint>

#define NROWS  131072
#define DIMD   512
#define KCOLS  1024
#define MT     128        // rows per CTA
#define NT     128        // cols per tile
#define KB     64         // d per chunk
#define NTILES (KCOLS/NT) // 8
#define DCH    (DIMD/KB)  // 8
#define NIT    (NTILES*DCH)  // 64
#define THREADS 512
#define NSTAGE 5          // B-only pipeline stages

// smem layout
#define SM_CSQ   0                    // 128 floats
#define SM_A     1024                 // resident A: 128 rows x 1024B (fp16, row-swizzled)
#define A_BYTES  (MT*DIMD*2)          // 131072
#define SM_B     (SM_A + A_BYTES)     // 132096
#define BSTG_B   (NT*KB*2)            // 16384 per stage
#define SMEM_TOTAL (SM_B + NSTAGE*BSTG_B)   // 214016

// ------------- device globals (no allocations allowed) -------------
__device__ __align__(128) __half g_Bhi[(size_t)KCOLS*DIMD];   // fp16 transposed [k][d]
__device__ __align__(128) float  g_Bt[(size_t)KCOLS*DIMD];    // fp32 transposed [k][d]
__device__ float g_csq[KCOLS];
__device__ int4  g_cand[NROWS];

// ------------- helpers -------------
__device__ __forceinline__ uint32_t smem_u32(const void* p) {
    uint32_t a;
    asm("{ .reg .u64 t; cvta.to.shared.u64 t, %1; cvt.u32.u64 %0, t; }" : "=r"(a) : "l"(p));
    return a;
}
__device__ __forceinline__ void cp16(uint32_t s, const void* g) {
    size_t ga = __cvta_generic_to_global(g);
    asm volatile("cp.async.cg.shared.global [%0], [%1], 16;" :: "r"(s), "l"(ga) : "memory");
}

#define LDM_X4(r0,r1,r2,r3,addr) \
    asm volatile("ldmatrix.sync.aligned.m8n8.x4.shared.b16 {%0,%1,%2,%3}, [%4];" \
        : "=r"(r0),"=r"(r1),"=r"(r2),"=r"(r3) : "r"(addr))

#define MMA16816(d, a, b0, b1) \
    asm volatile("mma.sync.aligned.m16n8k16.row.col.f32.f16.f16.f32 " \
        "{%0,%1,%2,%3},{%4,%5,%6,%7},{%8,%9},{%0,%1,%2,%3};" \
        : "+f"((d)[0]),"+f"((d)[1]),"+f"((d)[2]),"+f"((d)[3]) \
        : "r"((a)[0]),"r"((a)[1]),"r"((a)[2]),"r"((a)[3]),"r"(b0),"r"(b1))

// ------------- precompute kernels -------------
__global__ void split_cent(const float* __restrict__ B) {
    int i = blockIdx.x * blockDim.x + threadIdx.x;   // over [k][d]
    if (i >= KCOLS * DIMD) return;
    int k = i / DIMD, d = i % DIMD;
    float x = B[(size_t)d * KCOLS + k];
    g_Bhi[i] = __float2half_rn(x);
    g_Bt[i]  = x;
}

__global__ void csq_kernel(const float* __restrict__ c) {
    int k = blockIdx.x * blockDim.x + threadIdx.x;
    if (k < KCOLS) {
        float s = 0.f;
        #pragma unroll 8
        for (int d = 0; d < DIMD; d++) {
            float v = c[(size_t)d * KCOLS + k];
            s += v * v;
        }
        g_csq[k] = s;
    }
}

// ------------- phase 1: A-resident 1-pass fp16 screen + top-2/thread -> top-4/row -------------
__global__ __launch_bounds__(THREADS, 1) void assign_mma(const float* __restrict__ Af) {
    extern __shared__ char smem[];
    const uint32_t sb = smem_u32(smem);
    const int tid = threadIdx.x;
    const int lane = tid & 31;
    const int w = tid >> 5;
    const int mw = w >> 2;          // 0..3 (M)
    const int nw = w & 3;           // 0..3 (N)
    const int row0 = blockIdx.x * MT;
    float* csq_s = reinterpret_cast<float*>(smem + SM_CSQ);

    // ---- B stage loader ----
    auto load_stage = [&](int stg, int it) {
        const int nt = it >> 3, dc = it & 7;
        uint32_t sbase = sb + SM_B + (uint32_t)stg * BSTG_B;
        #pragma unroll
        for (int q = 0; q < 2; q++) {
            int s = tid + THREADS * q;
            int col = s >> 3, u = s & 7;
            uint32_t so = ((uint32_t)col * 128 + (uint32_t)u * 16) ^ (((uint32_t)col & 7) << 4);
            size_t gb = (size_t)(nt * NT + col) * DIMD + dc * KB + u * 8;
            cp16(sbase + so, g_Bhi + gb);
        }
        asm volatile("cp.async.commit_group;" ::: "memory");
    };

    // ---- prologue: kick B pipeline, then convert A fp32 -> resident fp16 smem ----
    #pragma unroll
    for (int p = 0; p < NSTAGE - 1; p++) load_stage(p, p);

    {
        // 8192 groups of 8 floats; 512 threads x 16 groups
        #pragma unroll
        for (int q = 0; q < 16; q++) {
            int g = tid + THREADS * q;
            int r = g >> 6;                 // 64 groups per row
            int d0 = (g & 63) * 8;
            const float4* a4 = reinterpret_cast<const float4*>(
                Af + (size_t)(row0 + r) * DIMD + d0);
            float4 v0 = a4[0], v1 = a4[1];
            __half h[8];
            h[0] = __float2half_rn(v0.x); h[1] = __float2half_rn(v0.y);
            h[2] = __float2half_rn(v0.z); h[3] = __float2half_rn(v0.w);
            h[4] = __float2half_rn(v1.x); h[5] = __float2half_rn(v1.y);
            h[6] = __float2half_rn(v1.z); h[7] = __float2half_rn(v1.w);
            uint32_t off = (uint32_t)r * 1024 +
                           (((uint32_t)d0 * 2) ^ (((uint32_t)r & 7) << 4));
            *reinterpret_cast<uint4*>(smem + SM_A + off) = *reinterpret_cast<uint4*>(h);
        }
    }

    // ---- ldmatrix address precomputes ----
    uint32_t aRow[2], aXor[2], bBase[2], bXor[2];
    #pragma unroll
    for (int mi = 0; mi < 2; mi++) {
        int r = mw * 32 + mi * 16 + (lane & 15);
        aRow[mi] = sb + SM_A + (uint32_t)r * 1024;
        aXor[mi] = (uint32_t)(r & 7) << 4;
    }
    #pragma unroll
    for (int nb = 0; nb < 2; nb++) {
        int r = nw * 32 + nb * 16 + ((lane & 7) + ((lane >> 4) << 3));
        bBase[nb] = (uint32_t)r * 128;
        bXor[nb] = (uint32_t)(r & 7) << 4;
    }
    const uint32_t aU = (uint32_t)(lane >> 4) * 16;        // 0 or 16
    const uint32_t bU = (uint32_t)((lane >> 3) & 1) * 16;  // 0 or 16

    float acc1[2][4][4];
    float v1[4], v2[4];
    int   i1[4], i2[4];
    #pragma unroll
    for (int i = 0; i < 4; i++) { v1[i] = 3.4e38f; v2[i] = 3.4e38f; i1[i] = 0; i2[i] = 0; }

    for (int it = 0; it < NIT; it++) {
        const int nt = it >> 3, dc = it & 7, stg = it % NSTAGE;
        asm volatile("cp.async.wait_group %0;" :: "n"(NSTAGE - 2) : "memory");
        __syncthreads();   // stage `it` arrived; all warps done with slot being reloaded; A visible
        if (it + NSTAGE - 1 < NIT)
            load_stage((it + NSTAGE - 1) % NSTAGE, it + NSTAGE - 1);

        if (dc == 0) {
            if (tid < NT) csq_s[tid] = g_csq[nt * NT + tid];
            #pragma unroll
            for (int mi = 0; mi < 2; mi++)
                #pragma unroll
                for (int ni = 0; ni < 4; ni++)
                    #pragma unroll
                    for (int e = 0; e < 4; e++) acc1[mi][ni][e] = 0.f;
        }

        // ---- compute chunk: A from resident smem, B from stage ----
        const uint32_t aCol0 = (uint32_t)dc * 128;
        const uint32_t sbB = sb + SM_B + (uint32_t)stg * BSTG_B;
        #pragma unroll
        for (int k16 = 0; k16 < 4; k16++) {
            const uint32_t ka = (uint32_t)k16 * 32 + aU;
            const uint32_t kb = (uint32_t)k16 * 32 + bU;
            uint32_t ahi[2][4], bhi[2][4];
            #pragma unroll
            for (int mi = 0; mi < 2; mi++)
                LDM_X4(ahi[mi][0], ahi[mi][1], ahi[mi][2], ahi[mi][3],
                       aRow[mi] + aCol0 + (ka ^ aXor[mi]));
            #pragma unroll
            for (int nb = 0; nb < 2; nb++)
                LDM_X4(bhi[nb][0], bhi[nb][1], bhi[nb][2], bhi[nb][3],
                       sbB + bBase[nb] + (kb ^ bXor[nb]));
            #pragma unroll
            for (int mi = 0; mi < 2; mi++)
                #pragma unroll
                for (int ni = 0; ni < 4; ni++)
                    MMA16816(acc1[mi][ni], ahi[mi],
                             bhi[ni >> 1][(ni & 1) * 2], bhi[ni >> 1][(ni & 1) * 2 + 1]);
        }

        if (dc == DCH - 1) {
            // fold this column tile into per-thread top-2 (registers only)
            #pragma unroll
            for (int mi = 0; mi < 2; mi++)
                #pragma unroll
                for (int half = 0; half < 2; half++) {
                    const int rs = mi * 2 + half;
                    #pragma unroll
                    for (int ni = 0; ni < 4; ni++)
                        #pragma unroll
                        for (int e = 0; e < 2; e++) {
                            const int cl = nw * 32 + ni * 8 + (lane & 3) * 2 + e;
                            const int col = nt * NT + cl;
                            float dist = csq_s[cl] - 2.0f * acc1[mi][ni][half * 2 + e];
                            if (dist < v1[rs]) {
                                v2[rs] = v1[rs]; i2[rs] = i1[rs];
                                v1[rs] = dist;   i1[rs] = col;
                            } else if (dist < v2[rs]) {
                                v2[rs] = dist; i2[rs] = col;
                            }
                        }
                }
        }
    }
    __syncthreads();

    // ---- dump per-thread top-2 (16 threads per row) into (reused) B smem ----
    float4* cand = reinterpret_cast<float4*>(smem + SM_B);   // [row][slot]
    {
        const int slot = nw * 4 + (lane & 3);
        #pragma unroll
        for (int rs = 0; rs < 4; rs++) {
            int row = mw * 32 + rs * 8 + (lane >> 2);
            cand[row * 16 + slot] = make_float4(v1[rs], __int_as_float(i1[rs]),
                                                v2[rs], __int_as_float(i2[rs]));
        }
    }
    __syncthreads();

    // ---- one thread per row: top-4 of 32 candidates (lexicographic) ----
    if (tid < MT) {
        float t1 = 3.4e38f, t2 = 3.4e38f, t3 = 3.4e38f, t4 = 3.4e38f;
        int   j1 = 0, j2 = 0, j3 = 0, j4 = 0;
        #pragma unroll 4
        for (int t = 0; t < 16; t++) {
            float4 c = cand[tid * 16 + t];
            #pragma unroll
            for (int h = 0; h < 2; h++) {
                float v = h ? c.z : c.x;
                int   i = __float_as_int(h ? c.w : c.y);
                if (v < t1 || (v == t1 && i < j1)) {
                    t4 = t3; j4 = j3; t3 = t2; j3 = j2; t2 = t1; j2 = j1; t1 = v; j1 = i;
                } else if (v < t2 || (v == t2 && i < j2)) {
                    t4 = t3; j4 = j3; t3 = t2; j3 = j2; t2 = v; j2 = i;
                } else if (v < t3 || (v == t3 && i < j3)) {
                    t4 = t3; j4 = j3; t3 = v; j3 = i;
                } else if (v < t4 || (v == t4 && i < j4)) {
                    t4 = v; j4 = i;
                }
            }
        }
        g_cand[row0 + tid] = make_int4(j1, j2, j3, j4);
    }
}

// ------------- phase 2: exact fp32 rescue, 1 thread/row, 4 ILP chains -------------
__global__ __launch_bounds__(256) void rescue_kernel(const float* __restrict__ A,
                                                     float* __restrict__ out) {
    int row = blockIdx.x * blockDim.x + threadIdx.x;
    if (row >= NROWS) return;
    int4 cd = g_cand[row];
    const float4* a4 = reinterpret_cast<const float4*>(A + (size_t)row * DIMD);
    const float4* b0 = reinterpret_cast<const float4*>(g_Bt + (size_t)cd.x * DIMD);
    const float4* b1 = reinterpret_cast<const float4*>(g_Bt + (size_t)cd.y * DIMD);
    const float4* b2 = reinterpret_cast<const float4*>(g_Bt + (size_t)cd.z * DIMD);
    const float4* b3 = reinterpret_cast<const float4*>(g_Bt + (size_t)cd.w * DIMD);
    float a0 = 0.f, a1 = 0.f, a2 = 0.f, a3 = 0.f;
    #pragma unroll 4
    for (int i = 0; i < DIMD / 4; i++) {
        float4 av = a4[i];
        float4 w0 = b0[i], w1 = b1[i], w2 = b2[i], w3 = b3[i];
        a0 = fmaf(av.x, w0.x, a0); a0 = fmaf(av.y, w0.y, a0);
        a0 = fmaf(av.z, w0.z, a0); a0 = fmaf(av.w, w0.w, a0);
        a1 = fmaf(av.x, w1.x, a1); a1 = fmaf(av.y, w1.y, a1);
        a1 = fmaf(av.z, w1.z, a1); a1 = fmaf(av.w, w1.w, a1);
        a2 = fmaf(av.x, w2.x, a2); a2 = fmaf(av.y, w2.y, a2);
        a2 = fmaf(av.z, w2.z, a2); a2 = fmaf(av.w, w2.w, a2);
        a3 = fmaf(av.x, w3.x, a3); a3 = fmaf(av.y, w3.y, a3);
        a3 = fmaf(av.z, w3.z, a3); a3 = fmaf(av.w, w3.w, a3);
    }
    float d0 = g_csq[cd.x] - 2.0f * a0;
    float d1 = g_csq[cd.y] - 2.0f * a1;
    float d2 = g_csq[cd.z] - 2.0f * a2;
    float d3 = g_csq[cd.w] - 2.0f * a3;
    float bv = d0; int bi = cd.x;
    if (d1 < bv || (d1 == bv && cd.y < bi)) { bv = d1; bi = cd.y; }
    if (d2 < bv || (d2 == bv && cd.z < bi)) { bv = d2; bi = cd.z; }
    if (d3 < bv || (d3 == bv && cd.w < bi)) { bv = d3; bi = cd.w; }
    out[row] = (float)bi;
}

// ------------- launch -------------
extern "C" void kernel_launch(void* const* d_in, const int* in_sizes, int n_in,
                              void* d_out, int out_size) {
    const float* features  = (const float*)d_in[0];   // [131072, 512]
    const float* centroids = (const float*)d_in[1];   // [512, 1024]
    float* out = (float*)d_out;

    cudaFuncSetAttribute(assign_mma, cudaFuncAttributeMaxDynamicSharedMemorySize, SMEM_TOTAL);

    split_cent<<<(KCOLS * DIMD + 255) / 256, 256>>>(centroids);
    csq_kernel<<<(KCOLS + 255) / 256, 256>>>(centroids);
    assign_mma<<<NROWS / MT, THREADS, SMEM_TOTAL>>>(features);
    rescue_kernel<<<NROWS / 256, 256>>>(features, out);
}

// round 8
// speedup vs baseline: 1.8786x; 1.8786x over previous
#include <cuda_runtime.h>
#include <cuda_fp16.h>
#include <cstdint>

#define NROWS  131072
#define DIMD   512
#define KCOLS  1024
#define MT     128        // rows per CTA
#define NT     128        // cols per tile
#define KB     64         // d per chunk
#define NTILES (KCOLS/NT) // 8
#define DCH    (DIMD/KB)  // 8
#define NIT    (NTILES*DCH)
#define THREADS 512
#define NSTAGE 6

// smem layout
#define SM_CSQ   0                   // 128 floats
#define SM_TILES 1024
#define ARR_B    (128*128)           // 16384 bytes per [128][64] half array
#define STAGE_B  (2*ARR_B)           // Ahi, Bhi = 32KB
#define SMEM_TOTAL (SM_TILES + NSTAGE*STAGE_B)   // 197632

// ------------- device globals (no allocations allowed) -------------
__device__ __align__(128) __half g_Ahi[(size_t)NROWS*DIMD];
__device__ __align__(128) __half g_Bhi[(size_t)KCOLS*DIMD];   // transposed [k][d]
__device__ __align__(128) float  g_Bt[(size_t)KCOLS*DIMD];    // fp32 transposed [k][d]
__device__ float g_csq[KCOLS];
__device__ int4  g_cand[NROWS];

// ------------- helpers -------------
__device__ __forceinline__ uint32_t smem_u32(const void* p) {
    uint32_t a;
    asm("{ .reg .u64 t; cvta.to.shared.u64 t, %1; cvt.u32.u64 %0, t; }" : "=r"(a) : "l"(p));
    return a;
}
__device__ __forceinline__ uint32_t sw128(uint32_t o) { return o ^ ((o >> 3) & 0x70); }

__device__ __forceinline__ void cp16(uint32_t s, const void* g) {
    size_t ga = __cvta_generic_to_global(g);
    asm volatile("cp.async.cg.shared.global [%0], [%1], 16;" :: "r"(s), "l"(ga) : "memory");
}

#define LDM_X4(r0,r1,r2,r3,addr) \
    asm volatile("ldmatrix.sync.aligned.m8n8.x4.shared.b16 {%0,%1,%2,%3}, [%4];" \
        : "=r"(r0),"=r"(r1),"=r"(r2),"=r"(r3) : "r"(addr))

#define MMA16816(d, a, b0, b1) \
    asm volatile("mma.sync.aligned.m16n8k16.row.col.f32.f16.f16.f32 " \
        "{%0,%1,%2,%3},{%4,%5,%6,%7},{%8,%9},{%0,%1,%2,%3};" \
        : "+f"((d)[0]),"+f"((d)[1]),"+f"((d)[2]),"+f"((d)[3]) \
        : "r"((a)[0]),"r"((a)[1]),"r"((a)[2]),"r"((a)[3]),"r"(b0),"r"(b1))

// ------------- precompute kernels -------------
__global__ void split_feat(const float* __restrict__ A) {
    size_t i = (size_t)blockIdx.x * blockDim.x + threadIdx.x;   // 8 elems each
    if (i >= (size_t)NROWS * DIMD / 8) return;
    const float4* a4 = reinterpret_cast<const float4*>(A) + i * 2;
    float4 v0 = a4[0], v1 = a4[1];
    float x[8] = {v0.x, v0.y, v0.z, v0.w, v1.x, v1.y, v1.z, v1.w};
    __half h[8];
    #pragma unroll
    for (int j = 0; j < 8; j++) h[j] = __float2half_rn(x[j]);
    reinterpret_cast<uint4*>(g_Ahi)[i] = *reinterpret_cast<uint4*>(h);
}

__global__ void split_cent(const float* __restrict__ B) {
    int i = blockIdx.x * blockDim.x + threadIdx.x;   // over [k][d]
    if (i >= KCOLS * DIMD) return;
    int k = i / DIMD, d = i % DIMD;
    float x = B[(size_t)d * KCOLS + k];
    g_Bhi[i] = __float2half_rn(x);
    g_Bt[i]  = x;
}

__global__ void csq_kernel(const float* __restrict__ c) {
    int k = blockIdx.x * blockDim.x + threadIdx.x;
    if (k < KCOLS) {
        float s = 0.f;
        #pragma unroll 8
        for (int d = 0; d < DIMD; d++) {
            float v = c[(size_t)d * KCOLS + k];
            s += v * v;
        }
        g_csq[k] = s;
    }
}

// ------------- phase 1: 1-pass fp16 screening GEMM + top-2/thread -> top-4/row -------------
__global__ __launch_bounds__(THREADS, 1) void assign_mma() {
    extern __shared__ char smem[];
    const uint32_t sb = smem_u32(smem);
    const int tid = threadIdx.x;
    const int lane = tid & 31;
    const int w = tid >> 5;
    const int mw = w >> 2;          // 0..3 (M)
    const int nw = w & 3;           // 0..3 (N)
    const int row0 = blockIdx.x * MT;
    float* csq_s = reinterpret_cast<float*>(smem + SM_CSQ);

    // ldmatrix address precomputes
    uint32_t aBase[2], aM[2], bBase[2], bM[2];
    #pragma unroll
    for (int mi = 0; mi < 2; mi++) {
        int r = mw * 32 + mi * 16 + (lane & 15);
        aBase[mi] = (uint32_t)r * 128;
        aM[mi] = (uint32_t)(r & 7) * 16;
    }
    #pragma unroll
    for (int nb = 0; nb < 2; nb++) {
        int r = nw * 32 + nb * 16 + ((lane & 7) + ((lane >> 4) << 3));
        bBase[nb] = (uint32_t)r * 128;
        bM[nb] = (uint32_t)(r & 7) * 16;
    }
    const uint32_t aU = (uint32_t)(lane >> 4) * 16;        // 0 or 16
    const uint32_t bU = (uint32_t)((lane >> 3) & 1) * 16;  // 0 or 16

    float acc1[2][4][4];
    float v1[4], v2[4];
    int   i1[4], i2[4];
    #pragma unroll
    for (int i = 0; i < 4; i++) { v1[i] = 3.4e38f; v2[i] = 3.4e38f; i1[i] = 0; i2[i] = 0; }

    auto load_stage = [&](int stg, int nt, int dc) {
        uint32_t sbase = sb + SM_TILES + (uint32_t)stg * STAGE_B;
        #pragma unroll
        for (int q = 0; q < 2; q++) {
            int s = tid + THREADS * q;
            int r = s >> 3, u = s & 7;
            uint32_t so = sw128((uint32_t)r * 128 + (uint32_t)u * 16);
            size_t ga = (size_t)(row0 + r) * DIMD + dc * KB + u * 8;
            size_t gb = (size_t)(nt * NT + r) * DIMD + dc * KB + u * 8;
            cp16(sbase + so,          g_Ahi + ga);
            cp16(sbase + ARR_B + so,  g_Bhi + gb);
        }
        asm volatile("cp.async.commit_group;" ::: "memory");
    };

    // prologue: fill NSTAGE-1 stages
    #pragma unroll
    for (int p = 0; p < NSTAGE - 1; p++) load_stage(p, p >> 3, p & 7);

    for (int it = 0; it < NIT; it++) {
        const int nt = it >> 3, dc = it & 7, stg = it % NSTAGE;
        asm volatile("cp.async.wait_group %0;" :: "n"(NSTAGE - 2) : "memory");
        __syncthreads();   // stage `it` arrived AND all warps done with slot being reloaded
        if (it + NSTAGE - 1 < NIT)
            load_stage((it + NSTAGE - 1) % NSTAGE, (it + NSTAGE - 1) >> 3, (it + NSTAGE - 1) & 7);

        if (dc == 0) {
            if (tid < NT) csq_s[tid] = g_csq[nt * NT + tid];
            #pragma unroll
            for (int mi = 0; mi < 2; mi++)
                #pragma unroll
                for (int ni = 0; ni < 4; ni++)
                    #pragma unroll
                    for (int e = 0; e < 4; e++) acc1[mi][ni][e] = 0.f;
        }

        // ---- compute chunk ----
        const uint32_t sbase = sb + SM_TILES + (uint32_t)stg * STAGE_B;
        #pragma unroll
        for (int k16 = 0; k16 < 4; k16++) {
            const uint32_t ka = (uint32_t)k16 * 32 + aU;
            const uint32_t kb = (uint32_t)k16 * 32 + bU;
            uint32_t ahi[2][4], bhi[2][4];
            #pragma unroll
            for (int mi = 0; mi < 2; mi++)
                LDM_X4(ahi[mi][0], ahi[mi][1], ahi[mi][2], ahi[mi][3],
                       sbase + aBase[mi] + (ka ^ aM[mi]));
            #pragma unroll
            for (int nb = 0; nb < 2; nb++)
                LDM_X4(bhi[nb][0], bhi[nb][1], bhi[nb][2], bhi[nb][3],
                       sbase + ARR_B + bBase[nb] + (kb ^ bM[nb]));
            #pragma unroll
            for (int mi = 0; mi < 2; mi++)
                #pragma unroll
                for (int ni = 0; ni < 4; ni++)
                    MMA16816(acc1[mi][ni], ahi[mi],
                             bhi[ni >> 1][(ni & 1) * 2], bhi[ni >> 1][(ni & 1) * 2 + 1]);
        }

        if (dc == DCH - 1) {
            // fold this column tile into per-thread top-2 (registers only)
            #pragma unroll
            for (int mi = 0; mi < 2; mi++)
                #pragma unroll
                for (int half = 0; half < 2; half++) {
                    const int rs = mi * 2 + half;
                    #pragma unroll
                    for (int ni = 0; ni < 4; ni++)
                        #pragma unroll
                        for (int e = 0; e < 2; e++) {
                            const int cl = nw * 32 + ni * 8 + (lane & 3) * 2 + e;
                            const int col = nt * NT + cl;
                            float dist = csq_s[cl] - 2.0f * acc1[mi][ni][half * 2 + e];
                            if (dist < v1[rs]) {
                                v2[rs] = v1[rs]; i2[rs] = i1[rs];
                                v1[rs] = dist;   i1[rs] = col;
                            } else if (dist < v2[rs]) {
                                v2[rs] = dist; i2[rs] = col;
                            }
                        }
                }
        }
    }
    __syncthreads();

    // ---- dump all per-thread top-2 to smem: 16 threads per row x (v1,i1,v2,i2) ----
    float4* cand = reinterpret_cast<float4*>(smem + SM_TILES);   // [row][slot] slot=nw*4+(lane&3)
    {
        const int slot = nw * 4 + (lane & 3);
        #pragma unroll
        for (int rs = 0; rs < 4; rs++) {
            int row = mw * 32 + rs * 8 + (lane >> 2);
            cand[row * 16 + slot] = make_float4(v1[rs], __int_as_float(i1[rs]),
                                                v2[rs], __int_as_float(i2[rs]));
        }
    }
    __syncthreads();

    // ---- one thread per row: top-4 of 32 candidates (lexicographic) ----
    if (tid < MT) {
        float t1 = 3.4e38f, t2 = 3.4e38f, t3 = 3.4e38f, t4 = 3.4e38f;
        int   j1 = 0, j2 = 0, j3 = 0, j4 = 0;
        #pragma unroll 4
        for (int t = 0; t < 16; t++) {
            float4 c = cand[tid * 16 + t];
            #pragma unroll
            for (int h = 0; h < 2; h++) {
                float v = h ? c.z : c.x;
                int   i = __float_as_int(h ? c.w : c.y);
                if (v < t1 || (v == t1 && i < j1)) {
                    t4 = t3; j4 = j3; t3 = t2; j3 = j2; t2 = t1; j2 = j1; t1 = v; j1 = i;
                } else if (v < t2 || (v == t2 && i < j2)) {
                    t4 = t3; j4 = j3; t3 = t2; j3 = j2; t2 = v; j2 = i;
                } else if (v < t3 || (v == t3 && i < j3)) {
                    t4 = t3; j4 = j3; t3 = v; j3 = i;
                } else if (v < t4 || (v == t4 && i < j4)) {
                    t4 = v; j4 = i;
                }
            }
        }
        g_cand[row0 + tid] = make_int4(j1, j2, j3, j4);
    }
}

// ------------- phase 2: exact fp32 rescue — one warp per row, coalesced -------------
__global__ __launch_bounds__(256) void rescue_kernel(const float* __restrict__ A,
                                                     float* __restrict__ out) {
    const int row = blockIdx.x * 8 + (threadIdx.x >> 5);
    const int lane = threadIdx.x & 31;
    const int4 cd = g_cand[row];   // same addr across warp -> broadcast

    // A row: 32 lanes x 4 float4 = 512 floats, coalesced, kept in registers
    const float4* a4 = reinterpret_cast<const float4*>(A + (size_t)row * DIMD);
    float4 av[4];
    #pragma unroll
    for (int i = 0; i < 4; i++) av[i] = a4[lane + 32 * i];

    int cands[4] = {cd.x, cd.y, cd.z, cd.w};
    float bv = 3.4e38f;
    int   bi = 0x7FFFFFFF;
    #pragma unroll
    for (int c = 0; c < 4; c++) {
        const float4* b4 = reinterpret_cast<const float4*>(g_Bt + (size_t)cands[c] * DIMD);
        float s = 0.f;
        #pragma unroll
        for (int i = 0; i < 4; i++) {
            float4 bvq = b4[lane + 32 * i];   // coalesced; g_Bt is L2-hot (2MB)
            s = fmaf(av[i].x, bvq.x, s);
            s = fmaf(av[i].y, bvq.y, s);
            s = fmaf(av[i].z, bvq.z, s);
            s = fmaf(av[i].w, bvq.w, s);
        }
        #pragma unroll
        for (int o = 16; o > 0; o >>= 1) s += __shfl_xor_sync(0xFFFFFFFFu, s, o);
        float dist = g_csq[cands[c]] - 2.0f * s;
        if (dist < bv || (dist == bv && cands[c] < bi)) { bv = dist; bi = cands[c]; }
    }
    if (lane == 0) out[row] = (float)bi;
}

// ------------- launch -------------
extern "C" void kernel_launch(void* const* d_in, const int* in_sizes, int n_in,
                              void* d_out, int out_size) {
    const float* features  = (const float*)d_in[0];   // [131072, 512]
    const float* centroids = (const float*)d_in[1];   // [512, 1024]
    float* out = (float*)d_out;

    cudaFuncSetAttribute(assign_mma, cudaFuncAttributeMaxDynamicSharedMemorySize, SMEM_TOTAL);

    split_feat<<<(int)(((size_t)NROWS * DIMD / 8 + 255) / 256), 256>>>(features);
    split_cent<<<(KCOLS * DIMD + 255) / 256, 256>>>(centroids);
    csq_kernel<<<(KCOLS + 255) / 256, 256>>>(centroids);
    assign_mma<<<NROWS / MT, THREADS, SMEM_TOTAL>>>();
    rescue_kernel<<<NROWS / 8, 256>>>(features, out);
}

// round 9
// speedup vs baseline: 1.9926x; 1.0606x over previous
#include <cuda_runtime.h>
#include <cuda_fp16.h>
#include <cstdint>

#define NROWS  131072
#define DIMD   512
#define KCOLS  1024
#define MT     128        // rows per CTA
#define NT     128        // cols per tile
#define KB     128        // d per chunk (two 64-d sub-arrays)
#define NTILES (KCOLS/NT) // 8
#define DCH    (DIMD/KB)  // 4
#define NIT    (NTILES*DCH)  // 32
#define THREADS 512
#define NSTAGE 3

// smem layout
#define SM_CSQ   0                   // 128 floats
#define SM_TILES 1024
#define SUB_B    16384               // one [128 rows][64 d] half array
#define STAGE_B  (4*SUB_B)           // A0|A1|B0|B1 = 64KB
#define SMEM_TOTAL (SM_TILES + NSTAGE*STAGE_B)   // 197632

// ------------- device globals (no allocations allowed) -------------
__device__ __align__(128) __half g_Ahi[(size_t)NROWS*DIMD];
__device__ __align__(128) __half g_Bhi[(size_t)KCOLS*DIMD];   // transposed [k][d]
__device__ __align__(128) float  g_Bt[(size_t)KCOLS*DIMD];    // fp32 transposed [k][d]
__device__ float g_csq[KCOLS];
__device__ int4  g_cand[NROWS];

// ------------- helpers -------------
__device__ __forceinline__ uint32_t smem_u32(const void* p) {
    uint32_t a;
    asm("{ .reg .u64 t; cvta.to.shared.u64 t, %1; cvt.u32.u64 %0, t; }" : "=r"(a) : "l"(p));
    return a;
}
__device__ __forceinline__ uint32_t sw128(uint32_t o) { return o ^ ((o >> 3) & 0x70); }

__device__ __forceinline__ void cp16(uint32_t s, const void* g) {
    size_t ga = __cvta_generic_to_global(g);
    asm volatile("cp.async.cg.shared.global [%0], [%1], 16;" :: "r"(s), "l"(ga) : "memory");
}

#define LDM_X4(r0,r1,r2,r3,addr) \
    asm volatile("ldmatrix.sync.aligned.m8n8.x4.shared.b16 {%0,%1,%2,%3}, [%4];" \
        : "=r"(r0),"=r"(r1),"=r"(r2),"=r"(r3) : "r"(addr))

#define MMA16816(d, a, b0, b1) \
    asm volatile("mma.sync.aligned.m16n8k16.row.col.f32.f16.f16.f32 " \
        "{%0,%1,%2,%3},{%4,%5,%6,%7},{%8,%9},{%0,%1,%2,%3};" \
        : "+f"((d)[0]),"+f"((d)[1]),"+f"((d)[2]),"+f"((d)[3]) \
        : "r"((a)[0]),"r"((a)[1]),"r"((a)[2]),"r"((a)[3]),"r"(b0),"r"(b1))

// ------------- precompute kernels -------------
__global__ void split_feat(const float* __restrict__ A) {
    size_t i = (size_t)blockIdx.x * blockDim.x + threadIdx.x;   // 8 elems each
    if (i >= (size_t)NROWS * DIMD / 8) return;
    const float4* a4 = reinterpret_cast<const float4*>(A) + i * 2;
    float4 v0 = a4[0], v1 = a4[1];
    float x[8] = {v0.x, v0.y, v0.z, v0.w, v1.x, v1.y, v1.z, v1.w};
    __half h[8];
    #pragma unroll
    for (int j = 0; j < 8; j++) h[j] = __float2half_rn(x[j]);
    reinterpret_cast<uint4*>(g_Ahi)[i] = *reinterpret_cast<uint4*>(h);
}

__global__ void split_cent(const float* __restrict__ B) {
    int i = blockIdx.x * blockDim.x + threadIdx.x;   // over [k][d]
    if (i >= KCOLS * DIMD) return;
    int k = i / DIMD, d = i % DIMD;
    float x = B[(size_t)d * KCOLS + k];
    g_Bhi[i] = __float2half_rn(x);
    g_Bt[i]  = x;
}

__global__ void csq_kernel(const float* __restrict__ c) {
    int k = blockIdx.x * blockDim.x + threadIdx.x;
    if (k < KCOLS) {
        float s = 0.f;
        #pragma unroll 8
        for (int d = 0; d < DIMD; d++) {
            float v = c[(size_t)d * KCOLS + k];
            s += v * v;
        }
        g_csq[k] = s;
    }
}

// ------------- phase 1: 1-pass fp16 screening GEMM + top-2/thread -> top-4/row -------------
__global__ __launch_bounds__(THREADS, 1) void assign_mma() {
    extern __shared__ char smem[];
    const uint32_t sb = smem_u32(smem);
    const int tid = threadIdx.x;
    const int lane = tid & 31;
    const int w = tid >> 5;
    const int mw = w >> 2;          // 0..3 (M)
    const int nw = w & 3;           // 0..3 (N)
    const int row0 = blockIdx.x * MT;
    float* csq_s = reinterpret_cast<float*>(smem + SM_CSQ);

    // ldmatrix address precomputes (within a 64-d sub-array)
    uint32_t aBase[2], aM[2], bBase[2], bM[2];
    #pragma unroll
    for (int mi = 0; mi < 2; mi++) {
        int r = mw * 32 + mi * 16 + (lane & 15);
        aBase[mi] = (uint32_t)r * 128;
        aM[mi] = (uint32_t)(r & 7) * 16;
    }
    #pragma unroll
    for (int nb = 0; nb < 2; nb++) {
        int r = nw * 32 + nb * 16 + ((lane & 7) + ((lane >> 4) << 3));
        bBase[nb] = (uint32_t)r * 128;
        bM[nb] = (uint32_t)(r & 7) * 16;
    }
    const uint32_t aU = (uint32_t)(lane >> 4) * 16;        // 0 or 16
    const uint32_t bU = (uint32_t)((lane >> 3) & 1) * 16;  // 0 or 16

    float acc1[2][4][4];
    float v1[4], v2[4];
    int   i1[4], i2[4];
    #pragma unroll
    for (int i = 0; i < 4; i++) { v1[i] = 3.4e38f; v2[i] = 3.4e38f; i1[i] = 0; i2[i] = 0; }

    // stage = A0|A1|B0|B1, each [128 rows][64 d] with the proven sw128 layout
    auto load_stage = [&](int stg, int it) {
        const int nt = it >> 2, dc = it & 3;
        uint32_t sbase = sb + SM_TILES + (uint32_t)stg * STAGE_B;
        #pragma unroll
        for (int q = 0; q < 8; q++) {
            int idx = tid + THREADS * q;          // 0..4095 16B units
            int arr = idx >> 10;                  // 0:A0 1:A1 2:B0 3:B1
            int rem = idx & 1023;
            int r = rem >> 3, u = rem & 7;
            uint32_t so = sw128((uint32_t)r * 128 + (uint32_t)u * 16);
            int d0 = dc * KB + (arr & 1) * 64 + u * 8;
            const __half* src = (arr < 2)
                ? g_Ahi + (size_t)(row0 + r) * DIMD + d0
                : g_Bhi + (size_t)(nt * NT + r) * DIMD + d0;
            cp16(sbase + (uint32_t)arr * SUB_B + so, src);
        }
        asm volatile("cp.async.commit_group;" ::: "memory");
    };

    // prologue: fill NSTAGE-1 stages
    load_stage(0, 0);
    load_stage(1, 1);

    for (int it = 0; it < NIT; it++) {
        const int nt = it >> 2, dc = it & 3, stg = it % NSTAGE;
        asm volatile("cp.async.wait_group %0;" :: "n"(NSTAGE - 2) : "memory");
        __syncthreads();   // stage `it` arrived AND all warps done with slot being reloaded
        if (it + NSTAGE - 1 < NIT)
            load_stage((it + NSTAGE - 1) % NSTAGE, it + NSTAGE - 1);

        if (dc == 0) {
            if (tid < NT) csq_s[tid] = g_csq[nt * NT + tid];
            #pragma unroll
            for (int mi = 0; mi < 2; mi++)
                #pragma unroll
                for (int ni = 0; ni < 4; ni++)
                    #pragma unroll
                    for (int e = 0; e < 4; e++) acc1[mi][ni][e] = 0.f;
        }

        // ---- compute chunk: 8 k16-steps (two 64-d sub-arrays) ----
        const uint32_t sbase = sb + SM_TILES + (uint32_t)stg * STAGE_B;
        #pragma unroll
        for (int k16 = 0; k16 < 8; k16++) {
            const uint32_t subA = sbase + (uint32_t)(k16 >> 2) * SUB_B;
            const uint32_t subB = sbase + 2 * SUB_B + (uint32_t)(k16 >> 2) * SUB_B;
            const uint32_t ka = (uint32_t)(k16 & 3) * 32 + aU;
            const uint32_t kb = (uint32_t)(k16 & 3) * 32 + bU;
            uint32_t ahi[2][4], bhi[2][4];
            #pragma unroll
            for (int mi = 0; mi < 2; mi++)
                LDM_X4(ahi[mi][0], ahi[mi][1], ahi[mi][2], ahi[mi][3],
                       subA + aBase[mi] + (ka ^ aM[mi]));
            #pragma unroll
            for (int nb = 0; nb < 2; nb++)
                LDM_X4(bhi[nb][0], bhi[nb][1], bhi[nb][2], bhi[nb][3],
                       subB + bBase[nb] + (kb ^ bM[nb]));
            #pragma unroll
            for (int mi = 0; mi < 2; mi++)
                #pragma unroll
                for (int ni = 0; ni < 4; ni++)
                    MMA16816(acc1[mi][ni], ahi[mi],
                             bhi[ni >> 1][(ni & 1) * 2], bhi[ni >> 1][(ni & 1) * 2 + 1]);
        }

        if (dc == DCH - 1) {
            // fold this column tile into per-thread top-2 (registers only)
            #pragma unroll
            for (int mi = 0; mi < 2; mi++)
                #pragma unroll
                for (int half = 0; half < 2; half++) {
                    const int rs = mi * 2 + half;
                    #pragma unroll
                    for (int ni = 0; ni < 4; ni++)
                        #pragma unroll
                        for (int e = 0; e < 2; e++) {
                            const int cl = nw * 32 + ni * 8 + (lane & 3) * 2 + e;
                            const int col = nt * NT + cl;
                            float dist = csq_s[cl] - 2.0f * acc1[mi][ni][half * 2 + e];
                            if (dist < v1[rs]) {
                                v2[rs] = v1[rs]; i2[rs] = i1[rs];
                                v1[rs] = dist;   i1[rs] = col;
                            } else if (dist < v2[rs]) {
                                v2[rs] = dist; i2[rs] = col;
                            }
                        }
                }
        }
    }
    __syncthreads();

    // ---- dump all per-thread top-2 to smem: 16 threads per row x (v1,i1,v2,i2) ----
    float4* cand = reinterpret_cast<float4*>(smem + SM_TILES);   // [row][slot] slot=nw*4+(lane&3)
    {
        const int slot = nw * 4 + (lane & 3);
        #pragma unroll
        for (int rs = 0; rs < 4; rs++) {
            int row = mw * 32 + rs * 8 + (lane >> 2);
            cand[row * 16 + slot] = make_float4(v1[rs], __int_as_float(i1[rs]),
                                                v2[rs], __int_as_float(i2[rs]));
        }
    }
    __syncthreads();

    // ---- one thread per row: top-4 of 32 candidates (lexicographic) ----
    if (tid < MT) {
        float t1 = 3.4e38f, t2 = 3.4e38f, t3 = 3.4e38f, t4 = 3.4e38f;
        int   j1 = 0, j2 = 0, j3 = 0, j4 = 0;
        #pragma unroll 4
        for (int t = 0; t < 16; t++) {
            float4 c = cand[tid * 16 + t];
            #pragma unroll
            for (int h = 0; h < 2; h++) {
                float v = h ? c.z : c.x;
                int   i = __float_as_int(h ? c.w : c.y);
                if (v < t1 || (v == t1 && i < j1)) {
                    t4 = t3; j4 = j3; t3 = t2; j3 = j2; t2 = t1; j2 = j1; t1 = v; j1 = i;
                } else if (v < t2 || (v == t2 && i < j2)) {
                    t4 = t3; j4 = j3; t3 = t2; j3 = j2; t2 = v; j2 = i;
                } else if (v < t3 || (v == t3 && i < j3)) {
                    t4 = t3; j4 = j3; t3 = v; j3 = i;
                } else if (v < t4 || (v == t4 && i < j4)) {
                    t4 = v; j4 = i;
                }
            }
        }
        g_cand[row0 + tid] = make_int4(j1, j2, j3, j4);
    }
}

// ------------- phase 2: exact fp32 rescue — one warp per row, coalesced -------------
__global__ __launch_bounds__(256) void rescue_kernel(const float* __restrict__ A,
                                                     float* __restrict__ out) {
    const int row = blockIdx.x * 8 + (threadIdx.x >> 5);
    const int lane = threadIdx.x & 31;
    const int4 cd = g_cand[row];   // same addr across warp -> broadcast

    // A row: 32 lanes x 4 float4 = 512 floats, coalesced, kept in registers
    const float4* a4 = reinterpret_cast<const float4*>(A + (size_t)row * DIMD);
    float4 av[4];
    #pragma unroll
    for (int i = 0; i < 4; i++) av[i] = a4[lane + 32 * i];

    int cands[4] = {cd.x, cd.y, cd.z, cd.w};
    float bv = 3.4e38f;
    int   bi = 0x7FFFFFFF;
    #pragma unroll
    for (int c = 0; c < 4; c++) {
        const float4* b4 = reinterpret_cast<const float4*>(g_Bt + (size_t)cands[c] * DIMD);
        float s = 0.f;
        #pragma unroll
        for (int i = 0; i < 4; i++) {
            float4 bvq = b4[lane + 32 * i];   // coalesced; g_Bt is L2-hot (2MB)
            s = fmaf(av[i].x, bvq.x, s);
            s = fmaf(av[i].y, bvq.y, s);
            s = fmaf(av[i].z, bvq.z, s);
            s = fmaf(av[i].w, bvq.w, s);
        }
        #pragma unroll
        for (int o = 16; o > 0; o >>= 1) s += __shfl_xor_sync(0xFFFFFFFFu, s, o);
        float dist = g_csq[cands[c]] - 2.0f * s;
        if (dist < bv || (dist == bv && cands[c] < bi)) { bv = dist; bi = cands[c]; }
    }
    if (lane == 0) out[row] = (float)bi;
}

// ------------- launch -------------
extern "C" void kernel_launch(void* const* d_in, const int* in_sizes, int n_in,
                              void* d_out, int out_size) {
    const float* features  = (const float*)d_in[0];   // [131072, 512]
    const float* centroids = (const float*)d_in[1];   // [512, 1024]
    float* out = (float*)d_out;

    cudaFuncSetAttribute(assign_mma, cudaFuncAttributeMaxDynamicSharedMemorySize, SMEM_TOTAL);

    split_feat<<<(int)(((size_t)NROWS * DIMD / 8 + 255) / 256), 256>>>(features);
    split_cent<<<(KCOLS * DIMD + 255) / 256, 256>>>(centroids);
    csq_kernel<<<(KCOLS + 255) / 256, 256>>>(centroids);
    assign_mma<<<NROWS / MT, THREADS, SMEM_TOTAL>>>();
    rescue_kernel<<<NROWS / 8, 256>>>(features, out);
}

// round 10
// speedup vs baseline: 2.0441x; 1.0259x over previous
#include <cuda_runtime.h>
#include <cuda_fp16.h>
#include <cstdint>

#define NROWS  131072
#define DIMD   512
#define KCOLS  1024
#define MT     64         // rows per CTA (2 CTAs/SM)
#define NT     128        // cols per tile
#define KB     64         // d per chunk
#define NTILES (KCOLS/NT) // 8
#define DCH    (DIMD/KB)  // 8
#define NIT    (NTILES*DCH)  // 64
#define THREADS 256
#define NSTAGE 4

// smem layout
#define SM_CSQ   0                   // 128 floats
#define SM_TILES 1024
#define A_SUB    8192                // [64 rows][64 d] half
#define B_SUB    16384               // [128 cols][64 d] half
#define STAGE_B  (A_SUB + B_SUB)     // 24KB
#define SMEM_TOTAL (SM_TILES + NSTAGE*STAGE_B)   // 99328 -> 2 CTAs = 198656

// ------------- device globals (no allocations allowed) -------------
__device__ __align__(128) __half g_Ahi[(size_t)NROWS*DIMD];
__device__ __align__(128) __half g_Bhi[(size_t)KCOLS*DIMD];   // transposed [k][d]
__device__ __align__(128) float  g_Bt[(size_t)KCOLS*DIMD];    // fp32 transposed [k][d]
__device__ float g_csq[KCOLS];
__device__ int4  g_cand[NROWS];

// ------------- helpers -------------
__device__ __forceinline__ uint32_t smem_u32(const void* p) {
    uint32_t a;
    asm("{ .reg .u64 t; cvta.to.shared.u64 t, %1; cvt.u32.u64 %0, t; }" : "=r"(a) : "l"(p));
    return a;
}
__device__ __forceinline__ uint32_t sw128(uint32_t o) { return o ^ ((o >> 3) & 0x70); }

__device__ __forceinline__ void cp16(uint32_t s, const void* g) {
    size_t ga = __cvta_generic_to_global(g);
    asm volatile("cp.async.cg.shared.global [%0], [%1], 16;" :: "r"(s), "l"(ga) : "memory");
}

#define LDM_X4(r0,r1,r2,r3,addr) \
    asm volatile("ldmatrix.sync.aligned.m8n8.x4.shared.b16 {%0,%1,%2,%3}, [%4];" \
        : "=r"(r0),"=r"(r1),"=r"(r2),"=r"(r3) : "r"(addr))

#define MMA16816(d, a, b0, b1) \
    asm volatile("mma.sync.aligned.m16n8k16.row.col.f32.f16.f16.f32 " \
        "{%0,%1,%2,%3},{%4,%5,%6,%7},{%8,%9},{%0,%1,%2,%3};" \
        : "+f"((d)[0]),"+f"((d)[1]),"+f"((d)[2]),"+f"((d)[3]) \
        : "r"((a)[0]),"r"((a)[1]),"r"((a)[2]),"r"((a)[3]),"r"(b0),"r"(b1))

// ------------- precompute kernels -------------
__global__ void split_feat(const float* __restrict__ A) {
    size_t i = (size_t)blockIdx.x * blockDim.x + threadIdx.x;   // 8 elems each
    if (i >= (size_t)NROWS * DIMD / 8) return;
    const float4* a4 = reinterpret_cast<const float4*>(A) + i * 2;
    float4 v0 = a4[0], v1 = a4[1];
    float x[8] = {v0.x, v0.y, v0.z, v0.w, v1.x, v1.y, v1.z, v1.w};
    __half h[8];
    #pragma unroll
    for (int j = 0; j < 8; j++) h[j] = __float2half_rn(x[j]);
    reinterpret_cast<uint4*>(g_Ahi)[i] = *reinterpret_cast<uint4*>(h);
}

__global__ void split_cent(const float* __restrict__ B) {
    int i = blockIdx.x * blockDim.x + threadIdx.x;   // over [k][d]
    if (i >= KCOLS * DIMD) return;
    int k = i / DIMD, d = i % DIMD;
    float x = B[(size_t)d * KCOLS + k];
    g_Bhi[i] = __float2half_rn(x);
    g_Bt[i]  = x;
}

__global__ void csq_kernel(const float* __restrict__ c) {
    int k = blockIdx.x * blockDim.x + threadIdx.x;
    if (k < KCOLS) {
        float s = 0.f;
        #pragma unroll 8
        for (int d = 0; d < DIMD; d++) {
            float v = c[(size_t)d * KCOLS + k];
            s += v * v;
        }
        g_csq[k] = s;
    }
}

// ------------- phase 1: 1-pass fp16 screening GEMM + top-2/thread -> top-4/row -------------
__global__ __launch_bounds__(THREADS, 2) void assign_mma() {
    extern __shared__ char smem[];
    const uint32_t sb = smem_u32(smem);
    const int tid = threadIdx.x;
    const int lane = tid & 31;
    const int w = tid >> 5;
    const int mw = w >> 2;          // 0..1 (M)
    const int nw = w & 3;           // 0..3 (N)
    const int row0 = blockIdx.x * MT;
    float* csq_s = reinterpret_cast<float*>(smem + SM_CSQ);

    // ldmatrix address precomputes (within a 64-d sub-array)
    uint32_t aBase[2], aM[2], bBase[2], bM[2];
    #pragma unroll
    for (int mi = 0; mi < 2; mi++) {
        int r = mw * 32 + mi * 16 + (lane & 15);
        aBase[mi] = (uint32_t)r * 128;
        aM[mi] = (uint32_t)(r & 7) * 16;
    }
    #pragma unroll
    for (int nb = 0; nb < 2; nb++) {
        int r = nw * 32 + nb * 16 + ((lane & 7) + ((lane >> 4) << 3));
        bBase[nb] = (uint32_t)r * 128;
        bM[nb] = (uint32_t)(r & 7) * 16;
    }
    const uint32_t aU = (uint32_t)(lane >> 4) * 16;        // 0 or 16
    const uint32_t bU = (uint32_t)((lane >> 3) & 1) * 16;  // 0 or 16

    float acc1[2][4][4];
    float v1[4], v2[4];
    int   i1[4], i2[4];
    #pragma unroll
    for (int i = 0; i < 4; i++) { v1[i] = 3.4e38f; v2[i] = 3.4e38f; i1[i] = 0; i2[i] = 0; }

    // stage = A(64x64d) | B(128x64d), proven sw128 layout within each
    auto load_stage = [&](int stg, int it) {
        const int nt = it >> 3, dc = it & 7;
        uint32_t sbase = sb + SM_TILES + (uint32_t)stg * STAGE_B;
        // A: 512 16B units
        #pragma unroll
        for (int q = 0; q < 2; q++) {
            int idx = tid + THREADS * q;
            int r = idx >> 3, u = idx & 7;
            uint32_t so = sw128((uint32_t)r * 128 + (uint32_t)u * 16);
            cp16(sbase + so, g_Ahi + (size_t)(row0 + r) * DIMD + dc * KB + u * 8);
        }
        // B: 1024 16B units
        #pragma unroll
        for (int q = 0; q < 4; q++) {
            int idx = tid + THREADS * q;
            int r = idx >> 3, u = idx & 7;
            uint32_t so = sw128((uint32_t)r * 128 + (uint32_t)u * 16);
            cp16(sbase + A_SUB + so, g_Bhi + (size_t)(nt * NT + r) * DIMD + dc * KB + u * 8);
        }
        asm volatile("cp.async.commit_group;" ::: "memory");
    };

    // prologue: fill NSTAGE-1 stages
    #pragma unroll
    for (int p = 0; p < NSTAGE - 1; p++) load_stage(p, p);

    for (int it = 0; it < NIT; it++) {
        const int nt = it >> 3, dc = it & 7, stg = it & (NSTAGE - 1);
        asm volatile("cp.async.wait_group %0;" :: "n"(NSTAGE - 2) : "memory");
        __syncthreads();   // stage `it` arrived AND all warps done with slot being reloaded
        if (it + NSTAGE - 1 < NIT)
            load_stage((it + NSTAGE - 1) & (NSTAGE - 1), it + NSTAGE - 1);

        if (dc == 0) {
            if (tid < NT) csq_s[tid] = g_csq[nt * NT + tid];
            #pragma unroll
            for (int mi = 0; mi < 2; mi++)
                #pragma unroll
                for (int ni = 0; ni < 4; ni++)
                    #pragma unroll
                    for (int e = 0; e < 4; e++) acc1[mi][ni][e] = 0.f;
        }

        // ---- compute chunk ----
        const uint32_t sbase = sb + SM_TILES + (uint32_t)stg * STAGE_B;
        #pragma unroll
        for (int k16 = 0; k16 < 4; k16++) {
            const uint32_t ka = (uint32_t)k16 * 32 + aU;
            const uint32_t kb = (uint32_t)k16 * 32 + bU;
            uint32_t ahi[2][4], bhi[2][4];
            #pragma unroll
            for (int mi = 0; mi < 2; mi++)
                LDM_X4(ahi[mi][0], ahi[mi][1], ahi[mi][2], ahi[mi][3],
                       sbase + aBase[mi] + (ka ^ aM[mi]));
            #pragma unroll
            for (int nb = 0; nb < 2; nb++)
                LDM_X4(bhi[nb][0], bhi[nb][1], bhi[nb][2], bhi[nb][3],
                       sbase + A_SUB + bBase[nb] + (kb ^ bM[nb]));
            #pragma unroll
            for (int mi = 0; mi < 2; mi++)
                #pragma unroll
                for (int ni = 0; ni < 4; ni++)
                    MMA16816(acc1[mi][ni], ahi[mi],
                             bhi[ni >> 1][(ni & 1) * 2], bhi[ni >> 1][(ni & 1) * 2 + 1]);
        }

        if (dc == DCH - 1) {
            // fold this column tile into per-thread top-2 (registers only)
            #pragma unroll
            for (int mi = 0; mi < 2; mi++)
                #pragma unroll
                for (int half = 0; half < 2; half++) {
                    const int rs = mi * 2 + half;
                    #pragma unroll
                    for (int ni = 0; ni < 4; ni++)
                        #pragma unroll
                        for (int e = 0; e < 2; e++) {
                            const int cl = nw * 32 + ni * 8 + (lane & 3) * 2 + e;
                            const int col = nt * NT + cl;
                            float dist = csq_s[cl] - 2.0f * acc1[mi][ni][half * 2 + e];
                            if (dist < v1[rs]) {
                                v2[rs] = v1[rs]; i2[rs] = i1[rs];
                                v1[rs] = dist;   i1[rs] = col;
                            } else if (dist < v2[rs]) {
                                v2[rs] = dist; i2[rs] = col;
                            }
                        }
                }
        }
    }
    __syncthreads();

    // ---- dump all per-thread top-2 to smem: 16 threads per row x (v1,i1,v2,i2) ----
    float4* cand = reinterpret_cast<float4*>(smem + SM_TILES);   // [row][slot] slot=nw*4+(lane&3)
    {
        const int slot = nw * 4 + (lane & 3);
        #pragma unroll
        for (int rs = 0; rs < 4; rs++) {
            int row = mw * 32 + rs * 8 + (lane >> 2);
            cand[row * 16 + slot] = make_float4(v1[rs], __int_as_float(i1[rs]),
                                                v2[rs], __int_as_float(i2[rs]));
        }
    }
    __syncthreads();

    // ---- one thread per row: top-4 of 32 candidates (lexicographic) ----
    if (tid < MT) {
        float t1 = 3.4e38f, t2 = 3.4e38f, t3 = 3.4e38f, t4 = 3.4e38f;
        int   j1 = 0, j2 = 0, j3 = 0, j4 = 0;
        #pragma unroll 4
        for (int t = 0; t < 16; t++) {
            float4 c = cand[tid * 16 + t];
            #pragma unroll
            for (int h = 0; h < 2; h++) {
                float v = h ? c.z : c.x;
                int   i = __float_as_int(h ? c.w : c.y);
                if (v < t1 || (v == t1 && i < j1)) {
                    t4 = t3; j4 = j3; t3 = t2; j3 = j2; t2 = t1; j2 = j1; t1 = v; j1 = i;
                } else if (v < t2 || (v == t2 && i < j2)) {
                    t4 = t3; j4 = j3; t3 = t2; j3 = j2; t2 = v; j2 = i;
                } else if (v < t3 || (v == t3 && i < j3)) {
                    t4 = t3; j4 = j3; t3 = v; j3 = i;
                } else if (v < t4 || (v == t4 && i < j4)) {
                    t4 = v; j4 = i;
                }
            }
        }
        g_cand[row0 + tid] = make_int4(j1, j2, j3, j4);
    }
}

// ------------- phase 2: exact fp32 rescue — one warp per row, coalesced -------------
__global__ __launch_bounds__(256) void rescue_kernel(const float* __restrict__ A,
                                                     float* __restrict__ out) {
    const int row = blockIdx.x * 8 + (threadIdx.x >> 5);
    const int lane = threadIdx.x & 31;
    const int4 cd = g_cand[row];   // same addr across warp -> broadcast

    // A row: 32 lanes x 4 float4 = 512 floats, coalesced, kept in registers
    const float4* a4 = reinterpret_cast<const float4*>(A + (size_t)row * DIMD);
    float4 av[4];
    #pragma unroll
    for (int i = 0; i < 4; i++) av[i] = a4[lane + 32 * i];

    int cands[4] = {cd.x, cd.y, cd.z, cd.w};
    float bv = 3.4e38f;
    int   bi = 0x7FFFFFFF;
    #pragma unroll
    for (int c = 0; c < 4; c++) {
        const float4* b4 = reinterpret_cast<const float4*>(g_Bt + (size_t)cands[c] * DIMD);
        float s = 0.f;
        #pragma unroll
        for (int i = 0; i < 4; i++) {
            float4 bvq = b4[lane + 32 * i];   // coalesced; g_Bt is L2-hot (2MB)
            s = fmaf(av[i].x, bvq.x, s);
            s = fmaf(av[i].y, bvq.y, s);
            s = fmaf(av[i].z, bvq.z, s);
            s = fmaf(av[i].w, bvq.w, s);
        }
        #pragma unroll
        for (int o = 16; o > 0; o >>= 1) s += __shfl_xor_sync(0xFFFFFFFFu, s, o);
        float dist = g_csq[cands[c]] - 2.0f * s;
        if (dist < bv || (dist == bv && cands[c] < bi)) { bv = dist; bi = cands[c]; }
    }
    if (lane == 0) out[row] = (float)bi;
}

// ------------- launch -------------
extern "C" void kernel_launch(void* const* d_in, const int* in_sizes, int n_in,
                              void* d_out, int out_size) {
    const float* features  = (const float*)d_in[0];   // [131072, 512]
    const float* centroids = (const float*)d_in[1];   // [512, 1024]
    float* out = (float*)d_out;

    cudaFuncSetAttribute(assign_mma, cudaFuncAttributeMaxDynamicSharedMemorySize, SMEM_TOTAL);

    split_feat<<<(int)(((size_t)NROWS * DIMD / 8 + 255) / 256), 256>>>(features);
    split_cent<<<(KCOLS * DIMD + 255) / 256, 256>>>(centroids);
    csq_kernel<<<(KCOLS + 255) / 256, 256>>>(centroids);
    assign_mma<<<NROWS / MT, THREADS, SMEM_TOTAL>>>();
    rescue_kernel<<<NROWS / 8, 256>>>(features, out);
}